// round 7
// baseline (speedup 1.0000x reference)
#include <cuda_runtime.h>
#include <cuda_bf16.h>
#include <cstdint>

// ---------------- dims ----------------
#define T_LEN  1024
#define NBG    16       // batch groups (16 batch each)
#define NGG    8        // gate-slice CTAs per group
#define NCG    8        // CTA-groups: each CTA serves groups (cg, cg+8)
#define BB     16

// ---------------- smem layout (bytes) ----------------
#define W_OFF   0
#define WPL     81920                  // per-plane W: [warp8][ks20][lane32][16B]
#define HXA_OFF 163840                 // hx group A: [plane2][ks20][lane32][16B]
#define HXB_OFF 184320
#define HXPL    10240
#define SP_OFF  204800                 // spill: [b16][136 floats]
#define SMEM_TOTAL 213504

// ---------------- static scratch ----------------
// hx ring in fragment layout: [t][bg]{hi 10240 | lo 10240}
__device__ char          g_B[(size_t)(T_LEN + 1) * NBG * 20480];
__device__ float         g_Hf[256][256];
__device__ unsigned int  g_cnt[NBG * 32];

// ---------------- helpers ----------------
__device__ __forceinline__ unsigned int ld_acq(const unsigned int* p) {
  unsigned int v;
  asm volatile("ld.acquire.gpu.global.u32 %0, [%1];" : "=r"(v) : "l"(p) : "memory");
  return v;
}
__device__ __forceinline__ void red_rel(unsigned int* p) {
  asm volatile("red.release.gpu.global.add.u32 [%0], 1;" :: "l"(p) : "memory");
}
__device__ __forceinline__ float fsig(float x) {
  x = fminf(fmaxf(x, -15.0f), 15.0f);
  return __fdividef(1.0f, 1.0f + __expf(-x));
}
__device__ __forceinline__ float ftanh(float x) {
  x = fminf(fmaxf(x, -15.0f), 15.0f);
  float e = __expf(-2.0f * x);
  return __fdividef(1.0f - e, 1.0f + e);
}
__device__ __forceinline__ void mma16816(float* d, const uint4& a,
                                         uint32_t b0, uint32_t b1) {
  asm volatile(
      "mma.sync.aligned.m16n8k16.row.col.f32.bf16.bf16.f32 "
      "{%0,%1,%2,%3}, {%4,%5,%6,%7}, {%8,%9}, {%0,%1,%2,%3};"
      : "+f"(d[0]), "+f"(d[1]), "+f"(d[2]), "+f"(d[3])
      : "r"(a.x), "r"(a.y), "r"(a.z), "r"(a.w), "r"(b0), "r"(b1));
}
// A/hx fragment offset for element (batch b, k_in) within one kstep's 512B frag
__device__ __forceinline__ int hx_frag_off(int b, int k_in) {
  int u    = (k_in & 7) >> 1;
  int half = k_in & 1;
  int reg  = ((b >> 3) & 1) + ((k_in >> 3) & 1) * 2;
  return ((b & 7) * 4 + u) * 16 + reg * 4 + half * 2;
}

// ---------------- prep kernels ----------------
__global__ void reset_kernel() {
  if (threadIdx.x < NBG * 32) g_cnt[threadIdx.x] = 0u;
}
// zero h-region (ks 0..15, both planes) of ring slot t=0 for all groups
__global__ void zring_kernel() {
  int id = blockIdx.x * 256 + threadIdx.x;   // 16384
  int bg = id >> 10, q = id & 1023;
  int off = (q >> 9) * 10240 + (q & 511) * 16;
  *(uint4*)(g_B + (size_t)bg * 20480 + off) = make_uint4(0, 0, 0, 0);
}
// stage x (hi/lo) into ring k-steps 16..19 for all t
__global__ void xprep_kernel(const float* __restrict__ x) {
  int id  = blockIdx.x * 256 + threadIdx.x;      // 16,777,216
  int i   = id & 63;
  int t   = (id >> 6) & 1023;
  int bgl = id >> 16;
  float v = x[(size_t)bgl * (T_LEN * 64) + t * 64 + i];
  __nv_bfloat16 hi = __float2bfloat16(v);
  __nv_bfloat16 lo = __float2bfloat16(v - __bfloat162float(hi));
  int bg = bgl >> 4, b = bgl & 15;
  int ks = 16 + (i >> 4);
  int off = ks * 512 + hx_frag_off(b, i & 15);
  char* base = g_B + ((size_t)t * NBG + bg) * 20480;
  *(__nv_bfloat16*)(base + off)         = hi;
  *(__nv_bfloat16*)(base + 10240 + off) = lo;
}

// ---------------- main persistent kernel ----------------
__global__ void __launch_bounds__(256, 1) lstm_kernel(
    const float* __restrict__ W_ih, const float* __restrict__ W_hh,
    const float* __restrict__ b_ih, const float* __restrict__ b_hh) {
  extern __shared__ char smem[];
  const int tid  = threadIdx.x;
  const int wz   = tid >> 5;
  const int lane = tid & 31;
  const int cg   = blockIdx.x >> 3;
  const int gg   = blockIdx.x & 7;
  const int c0   = gg * 32;
  const int bgA  = cg, bgB = cg + 8;

  // ---- one-time: W slice -> smem fragment-major; warp w owns rows w*16..w*16+15 ----
  for (int idx = tid; idx < 128 * 320; idx += 256) {
    int r = idx / 320, k = idx - r * 320;
    int gate = r >> 5;
    int gr = gate * 256 + c0 + (r & 31);
    float v = (k < 256) ? W_hh[gr * 256 + k] : W_ih[gr * 64 + (k - 256)];
    __nv_bfloat16 hi = __float2bfloat16(v);
    __nv_bfloat16 lo = __float2bfloat16(v - __bfloat162float(hi));
    int ks = k >> 4, ki = k & 15;
    int off = (r >> 4) * 10240 + ks * 512 +
              (((r & 7) * 4 + ((ki & 7) >> 1)) << 4) +
              ((r >> 3) & 1) * 8 + ((ki >> 3) & 1) * 4 + (ki & 1) * 2;
    *(__nv_bfloat16*)(smem + W_OFF + off)       = hi;
    *(__nv_bfloat16*)(smem + W_OFF + WPL + off) = lo;
  }

  // ring load/store chunk offsets: 5 x 16B per thread covers 20480B
  int hoff[5];
#pragma unroll
  for (int i = 0; i < 5; i++) {
    int q = tid + i * 256;
    hoff[i] = (q < 640) ? q * 16 : 10240 + (q - 640) * 16;
  }

  // epilogue mapping
  const int ehc = tid & 31;
  const int eb  = tid >> 5;
  const int eks = gg * 2 + (ehc >> 4);
  const int ekin = ehc & 15;
  float bias[4];
#pragma unroll
  for (int g = 0; g < 4; g++)
    bias[g] = b_ih[g * 256 + c0 + ehc] + b_hh[g * 256 + c0 + ehc];

  unsigned int* flagA = &g_cnt[bgA * 32];
  unsigned int* flagB = &g_cnt[bgB * 32];

  // ---- lambdas ----
  auto ldring = [&](const char* ring, uint4* hv) {
#pragma unroll
    for (int i = 0; i < 5; i++) hv[i] = __ldcg((const uint4*)(ring + hoff[i]));
  };
  auto stshx = [&](char* hx, const uint4* hv) {
#pragma unroll
    for (int i = 0; i < 5; i++) *(uint4*)(hx + hoff[i]) = hv[i];
    __syncthreads();
  };
  auto mmag = [&](const char* hx, float* acc) {
#pragma unroll
    for (int i = 0; i < 8; i++) acc[i] = 0.f;
    const char* pAh = hx + lane * 16;
    const char* pAl = pAh + HXPL;
    const char* pBh = smem + W_OFF + wz * 10240 + lane * 16;
    const char* pBl = pBh + WPL;
#pragma unroll
    for (int ks = 0; ks < 20; ks++) {
      uint4 aH = *(const uint4*)(pAh + ks * 512);
      uint4 aL = *(const uint4*)(pAl + ks * 512);
      uint4 bH = *(const uint4*)(pBh + ks * 512);
      uint4 bL = *(const uint4*)(pBl + ks * 512);
      mma16816(acc,     aH, bH.x, bH.y);
      mma16816(acc,     aH, bL.x, bL.y);
      mma16816(acc,     aL, bH.x, bH.y);
      mma16816(acc + 4, aH, bH.z, bH.w);
      mma16816(acc + 4, aH, bL.z, bL.w);
      mma16816(acc + 4, aL, bH.z, bH.w);
    }
  };
  // spill + epilogue + publish + release for one group
  auto phase2 = [&](float* acc, float* cs, char* ringT1, unsigned int* flag,
                    int bg, bool last) {
    float* sp = (float*)(smem + SP_OFF);
    {
      int q = lane >> 2, cp2 = (lane & 3) * 2;
      *(float2*)(sp + q * 136 + wz * 16 + cp2)           = make_float2(acc[0], acc[1]);
      *(float2*)(sp + (q + 8) * 136 + wz * 16 + cp2)     = make_float2(acc[2], acc[3]);
      *(float2*)(sp + q * 136 + wz * 16 + 8 + cp2)       = make_float2(acc[4], acc[5]);
      *(float2*)(sp + (q + 8) * 136 + wz * 16 + 8 + cp2) = make_float2(acc[6], acc[7]);
    }
    __syncthreads();
#pragma unroll
    for (int uu = 0; uu < 2; uu++) {
      int b = eb + uu * 8;
      float gi = sp[b * 136 +  0 + ehc] + bias[0];
      float gf = sp[b * 136 + 32 + ehc] + bias[1];
      float gc = sp[b * 136 + 64 + ehc] + bias[2];
      float go = sp[b * 136 + 96 + ehc] + bias[3];
      float iv = fsig(gi), fv = fsig(gf), cv = ftanh(gc), ov = fsig(go);
      float cn = fv * cs[uu] + iv * cv;
      cs[uu] = cn;
      float hv = ov * ftanh(cn);
      __nv_bfloat16 hi = __float2bfloat16(hv);
      __nv_bfloat16 lo = __float2bfloat16(hv - __bfloat162float(hi));
      int off = eks * 512 + hx_frag_off(b, ekin);
      *(__nv_bfloat16*)(ringT1 + off)         = hi;
      *(__nv_bfloat16*)(ringT1 + 10240 + off) = lo;
      if (last) g_Hf[bg * BB + b][c0 + ehc] = hv;
    }
    __syncthreads();
    if (tid == 0) red_rel(flag);
  };

  float csA[2] = {0.f, 0.f}, csB[2] = {0.f, 0.f};
  float accA[8], accB[8];
  uint4 hv[5];

  __syncthreads();   // W fill complete (also covered by stshx sync, kept for clarity)

  // ---- prologue: t = 0 ----
  ldring(g_B + (size_t)bgA * 20480, hv);
  stshx(smem + HXA_OFF, hv);
  mmag(smem + HXA_OFF, accA);
  ldring(g_B + (size_t)bgB * 20480, hv);
  phase2(accA, csA, g_B + ((size_t)NBG + bgA) * 20480, flagA, bgA, false);
  stshx(smem + HXB_OFF, hv);
  mmag(smem + HXB_OFF, accB);

  // ---- pipelined main loop ----
  for (int t = 1; t < T_LEN; t++) {
    {
      unsigned int target = (unsigned int)(NGG * t);
      while (ld_acq(flagA) < target) { }
      ldring(g_B + ((size_t)t * NBG + bgA) * 20480, hv);
    }
    phase2(accB, csB, g_B + ((size_t)t * NBG + bgB) * 20480, flagB, bgB, false);
    stshx(smem + HXA_OFF, hv);
    mmag(smem + HXA_OFF, accA);
    {
      unsigned int target = (unsigned int)(NGG * t);
      while (ld_acq(flagB) < target) { }
      ldring(g_B + ((size_t)t * NBG + bgB) * 20480, hv);
    }
    phase2(accA, csA, g_B + ((size_t)(t + 1) * NBG + bgA) * 20480, flagA, bgA,
           t == T_LEN - 1);
    stshx(smem + HXB_OFF, hv);
    mmag(smem + HXB_OFF, accB);
  }
  phase2(accB, csB, g_B + ((size_t)T_LEN * NBG + bgB) * 20480, flagB, bgB, true);
}

// ---------------- fc ----------------
__global__ void fc_kernel(const float* __restrict__ fc_w,
                          const float* __restrict__ fc_b,
                          float* __restrict__ out) {
  int b = blockIdx.x;
  float s = g_Hf[b][threadIdx.x] * fc_w[threadIdx.x];
#pragma unroll
  for (int o = 16; o; o >>= 1) s += __shfl_xor_sync(0xFFFFFFFFu, s, o);
  __shared__ float ps[8];
  if ((threadIdx.x & 31) == 0) ps[threadIdx.x >> 5] = s;
  __syncthreads();
  if (threadIdx.x == 0) {
    float tt = 0.f;
#pragma unroll
    for (int i = 0; i < 8; i++) tt += ps[i];
    out[b] = tt + fc_b[0];
  }
}

// ---------------- launch ----------------
extern "C" void kernel_launch(void* const* d_in, const int* in_sizes, int n_in,
                              void* d_out, int out_size) {
  const float* x    = (const float*)d_in[0];
  const float* W_ih = (const float*)d_in[1];
  const float* W_hh = (const float*)d_in[2];
  const float* b_ih = (const float*)d_in[3];
  const float* b_hh = (const float*)d_in[4];
  const float* fc_w = (const float*)d_in[5];
  const float* fc_b = (const float*)d_in[6];
  float* out = (float*)d_out;

  static bool init = false;
  if (!init) {
    cudaFuncSetAttribute(lstm_kernel,
                         cudaFuncAttributeMaxDynamicSharedMemorySize, SMEM_TOTAL);
    init = true;
  }

  reset_kernel<<<1, 512>>>();
  zring_kernel<<<64, 256>>>();
  xprep_kernel<<<65536, 256>>>(x);
  lstm_kernel<<<NCG * NGG, 256, SMEM_TOTAL>>>(W_ih, W_hh, b_ih, b_hh);
  fc_kernel<<<256, 256>>>(fc_w, fc_b, out);
}

// round 8
// speedup vs baseline: 1.7022x; 1.7022x over previous
#include <cuda_runtime.h>
#include <cuda_bf16.h>
#include <cstdint>

// ---------------- dims ----------------
#define T_LEN  1024
#define NBG    16       // batch groups (16 batch each)
#define NGG    8        // gate-slice CTAs per group
#define BB     16
#define NTHR   512

// ---------------- smem layout (bytes) ----------------
#define W_OFF   0
#define WPL     81920                  // per-plane W frags: [rg8][ks20][lane32][16B]
#define HX_OFF  163840                 // hx: [plane2][ks20][lane32][16B]
#define HXPL    10240
#define SP_OFF  184320                 // spill: [kh2][b16][136 floats]
#define SP_HALF 8704
#define SMEM_TOTAL (SP_OFF + 2 * SP_HALF)   // 201728

// ---------------- static scratch ----------------
// hx ring in fragment layout: [t][bg]{hi 10240 | lo 10240}
__device__ char          g_B[(size_t)(T_LEN + 1) * NBG * 20480];
__device__ float         g_Hf[256][256];
__device__ unsigned int  g_cnt[NBG * 32];

// ---------------- helpers ----------------
__device__ __forceinline__ unsigned int ld_acq(const unsigned int* p) {
  unsigned int v;
  asm volatile("ld.acquire.gpu.global.u32 %0, [%1];" : "=r"(v) : "l"(p) : "memory");
  return v;
}
__device__ __forceinline__ void red_rel(unsigned int* p) {
  asm volatile("red.release.gpu.global.add.u32 [%0], 1;" :: "l"(p) : "memory");
}
__device__ __forceinline__ float fsig(float x) {
  x = fminf(fmaxf(x, -15.0f), 15.0f);
  return __fdividef(1.0f, 1.0f + __expf(-x));
}
__device__ __forceinline__ float ftanh(float x) {
  x = fminf(fmaxf(x, -15.0f), 15.0f);
  float e = __expf(-2.0f * x);
  return __fdividef(1.0f - e, 1.0f + e);
}
__device__ __forceinline__ void mma16816(float* d, const uint4& a,
                                         uint32_t b0, uint32_t b1) {
  asm volatile(
      "mma.sync.aligned.m16n8k16.row.col.f32.bf16.bf16.f32 "
      "{%0,%1,%2,%3}, {%4,%5,%6,%7}, {%8,%9}, {%0,%1,%2,%3};"
      : "+f"(d[0]), "+f"(d[1]), "+f"(d[2]), "+f"(d[3])
      : "r"(a.x), "r"(a.y), "r"(a.z), "r"(a.w), "r"(b0), "r"(b1));
}
// hx fragment offset for element (batch b, k_in) within one kstep's 512B frag
__device__ __forceinline__ int hx_frag_off(int b, int k_in) {
  int u    = (k_in & 7) >> 1;
  int half = k_in & 1;
  int reg  = ((b >> 3) & 1) + ((k_in >> 3) & 1) * 2;
  return ((b & 7) * 4 + u) * 16 + reg * 4 + half * 2;
}

// ---------------- prep kernels ----------------
__global__ void reset_kernel() {
  if (threadIdx.x < NBG * 32) g_cnt[threadIdx.x] = 0u;
}
// zero h-region (ks 0..15, both planes) of ring slot 0 for all groups
__global__ void zring_kernel() {
  int id = blockIdx.x * 256 + threadIdx.x;   // 16384
  int bg = id >> 10, q = id & 1023;
  int off = (q >> 9) * 10240 + (q & 511) * 16;
  *(uint4*)(g_B + (size_t)bg * 20480 + off) = make_uint4(0, 0, 0, 0);
}
// stage x (hi/lo) into ring k-steps 16..19 for all t
__global__ void xprep_kernel(const float* __restrict__ x) {
  int id  = blockIdx.x * 256 + threadIdx.x;      // 16,777,216
  int i   = id & 63;
  int t   = (id >> 6) & 1023;
  int bgl = id >> 16;
  float v = x[(size_t)bgl * (T_LEN * 64) + t * 64 + i];
  __nv_bfloat16 hi = __float2bfloat16(v);
  __nv_bfloat16 lo = __float2bfloat16(v - __bfloat162float(hi));
  int bg = bgl >> 4, b = bgl & 15;
  int ks = 16 + (i >> 4);
  int off = ks * 512 + hx_frag_off(b, i & 15);
  char* base = g_B + ((size_t)t * NBG + bg) * 20480;
  *(__nv_bfloat16*)(base + off)         = hi;
  *(__nv_bfloat16*)(base + 10240 + off) = lo;
}

// ---------------- main persistent kernel ----------------
__global__ void __launch_bounds__(NTHR, 1) lstm_kernel(
    const float* __restrict__ W_ih, const float* __restrict__ W_hh,
    const float* __restrict__ b_ih, const float* __restrict__ b_hh) {
  extern __shared__ char smem[];
  const int tid  = threadIdx.x;
  const int wz   = tid >> 5;
  const int lane = tid & 31;
  const int bg   = blockIdx.x >> 3;
  const int gg   = blockIdx.x & 7;
  const int c0   = gg * 32;

  // ---- one-time: W slice -> smem fragment-major; row-group rg owns rows rg*16.. ----
  for (int idx = tid; idx < 128 * 320; idx += NTHR) {
    int r = idx / 320, k = idx - r * 320;
    int gate = r >> 5;
    int gr = gate * 256 + c0 + (r & 31);
    float v = (k < 256) ? W_hh[gr * 256 + k] : W_ih[gr * 64 + (k - 256)];
    __nv_bfloat16 hi = __float2bfloat16(v);
    __nv_bfloat16 lo = __float2bfloat16(v - __bfloat162float(hi));
    int ks = k >> 4, ki = k & 15;
    int off = (r >> 4) * 10240 + ks * 512 +
              (((r & 7) * 4 + ((ki & 7) >> 1)) << 4) +
              ((r >> 3) & 1) * 8 + ((ki >> 3) & 1) * 4 + (ki & 1) * 2;
    *(__nv_bfloat16*)(smem + W_OFF + off)       = hi;
    *(__nv_bfloat16*)(smem + W_OFF + WPL + off) = lo;
  }

  // h copy-in: 2 x 16B chunks per thread (16KB h region, both planes)
  int hoff[2];
#pragma unroll
  for (int i = 0; i < 2; i++) {
    int q = tid + i * NTHR;
    hoff[i] = (q >> 9) * 10240 + (q & 511) * 16;
  }
  // x stage: tid<256, one 16B chunk (4KB x region, both planes)
  const int xoff = (tid >> 7) * 10240 + 8192 + (tid & 127) * 16;

  // ---- MMA mapping: rg = row group (16 rows), kh = interleaved k-half ----
  const int rg = wz & 7;
  const int kh = wz >> 3;
  const char* pAh = smem + HX_OFF + kh * 512 + lane * 16;   // + j*1024
  const char* pAl = pAh + HXPL;
  const char* pBh = smem + W_OFF + rg * 10240 + kh * 512 + lane * 16;
  const char* pBl = pBh + WPL;

  // ---- epilogue mapping: one (b, hc) element per thread ----
  const int eb  = tid >> 5;
  const int ehc = tid & 31;
  const int eks = gg * 2 + (ehc >> 4);
  const int ekin = ehc & 15;
  float bias[4];
#pragma unroll
  for (int g = 0; g < 4; g++)
    bias[g] = b_ih[g * 256 + c0 + ehc] + b_hh[g * 256 + c0 + ehc];
  float cs = 0.f;

  unsigned int* flag = &g_cnt[bg * 32];

  // prologue: stage x(0)
  if (tid < 256) {
    const char* src = g_B + (size_t)bg * 20480;
    *(uint4*)(smem + HX_OFF + xoff) = __ldcg((const uint4*)(src + xoff));
  }
  __syncthreads();

  for (int t = 0; t < T_LEN; t++) {
    const char* ringT  = g_B + ((size_t)t * NBG + bg) * 20480;
    char*       ringT1 = g_B + ((size_t)(t + 1) * NBG + bg) * 20480;

    // ---- wait for h(t), then issue h LDGs + x(t+1) prefetch ----
    if (t) {
      unsigned int target = (unsigned int)(NGG * t);
      while (ld_acq(flag) < target) { }
    }
    uint4 hv0 = __ldcg((const uint4*)(ringT + hoff[0]));
    uint4 hv1 = __ldcg((const uint4*)(ringT + hoff[1]));
    uint4 xv;
    if (tid < 256) xv = __ldcg((const uint4*)(ringT1 + xoff));

    float acc[8];
#pragma unroll
    for (int i = 0; i < 8; i++) acc[i] = 0.f;

    // ---- x-part MMAs (j = 8,9 -> ksteps 16..19) while h LDGs fly ----
#pragma unroll
    for (int j = 8; j < 10; j++) {
      uint4 aH = *(const uint4*)(pAh + j * 1024);
      uint4 aL = *(const uint4*)(pAl + j * 1024);
      uint4 bH = *(const uint4*)(pBh + j * 1024);
      uint4 bL = *(const uint4*)(pBl + j * 1024);
      mma16816(acc,     aH, bH.x, bH.y);
      mma16816(acc,     aH, bL.x, bL.y);
      mma16816(acc,     aL, bH.x, bH.y);
      mma16816(acc + 4, aH, bH.z, bH.w);
      mma16816(acc + 4, aH, bL.z, bL.w);
      mma16816(acc + 4, aL, bH.z, bH.w);
    }

    // ---- land h frags ----
    *(uint4*)(smem + HX_OFF + hoff[0]) = hv0;
    *(uint4*)(smem + HX_OFF + hoff[1]) = hv1;
    __syncthreads();

    // ---- h-part MMAs (j = 0..7 -> ksteps 0..15) ----
#pragma unroll
    for (int j = 0; j < 8; j++) {
      uint4 aH = *(const uint4*)(pAh + j * 1024);
      uint4 aL = *(const uint4*)(pAl + j * 1024);
      uint4 bH = *(const uint4*)(pBh + j * 1024);
      uint4 bL = *(const uint4*)(pBl + j * 1024);
      mma16816(acc,     aH, bH.x, bH.y);
      mma16816(acc,     aH, bL.x, bL.y);
      mma16816(acc,     aL, bH.x, bH.y);
      mma16816(acc + 4, aH, bH.z, bH.w);
      mma16816(acc + 4, aH, bL.z, bL.w);
      mma16816(acc + 4, aL, bH.z, bH.w);
    }

    // ---- spill partial D: [kh][b][136] ----
    {
      int q = lane >> 2, cp2 = (lane & 3) * 2;
      float* sp = (float*)(smem + SP_OFF + kh * SP_HALF);
      *(float2*)(sp + q * 136 + rg * 16 + cp2)           = make_float2(acc[0], acc[1]);
      *(float2*)(sp + (q + 8) * 136 + rg * 16 + cp2)     = make_float2(acc[2], acc[3]);
      *(float2*)(sp + q * 136 + rg * 16 + 8 + cp2)       = make_float2(acc[4], acc[5]);
      *(float2*)(sp + (q + 8) * 136 + rg * 16 + 8 + cp2) = make_float2(acc[6], acc[7]);
    }
    __syncthreads();

    // ---- epilogue: combine halves, activations, publish h(t+1), stage x(t+1) ----
    {
      const float* s0 = (const float*)(smem + SP_OFF);
      const float* s1 = (const float*)(smem + SP_OFF + SP_HALF);
      float gi = s0[eb * 136 +  0 + ehc] + s1[eb * 136 +  0 + ehc] + bias[0];
      float gf = s0[eb * 136 + 32 + ehc] + s1[eb * 136 + 32 + ehc] + bias[1];
      float gc = s0[eb * 136 + 64 + ehc] + s1[eb * 136 + 64 + ehc] + bias[2];
      float go = s0[eb * 136 + 96 + ehc] + s1[eb * 136 + 96 + ehc] + bias[3];
      float iv = fsig(gi), fv = fsig(gf), cv = ftanh(gc), ov = fsig(go);
      float cn = fv * cs + iv * cv;
      cs = cn;
      float hvv = ov * ftanh(cn);
      __nv_bfloat16 hi = __float2bfloat16(hvv);
      __nv_bfloat16 lo = __float2bfloat16(hvv - __bfloat162float(hi));
      int off = eks * 512 + hx_frag_off(eb, ekin);
      *(__nv_bfloat16*)(ringT1 + off)         = hi;
      *(__nv_bfloat16*)(ringT1 + 10240 + off) = lo;
      if (t == T_LEN - 1) g_Hf[bg * BB + eb][c0 + ehc] = hvv;
      if (tid < 256) *(uint4*)(smem + HX_OFF + xoff) = xv;
    }
    __syncthreads();
    if (tid == 0) red_rel(flag);
  }
}

// ---------------- fc ----------------
__global__ void fc_kernel(const float* __restrict__ fc_w,
                          const float* __restrict__ fc_b,
                          float* __restrict__ out) {
  int b = blockIdx.x;
  float s = g_Hf[b][threadIdx.x] * fc_w[threadIdx.x];
#pragma unroll
  for (int o = 16; o; o >>= 1) s += __shfl_xor_sync(0xFFFFFFFFu, s, o);
  __shared__ float ps[8];
  if ((threadIdx.x & 31) == 0) ps[threadIdx.x >> 5] = s;
  __syncthreads();
  if (threadIdx.x == 0) {
    float tt = 0.f;
#pragma unroll
    for (int i = 0; i < 8; i++) tt += ps[i];
    out[b] = tt + fc_b[0];
  }
}

// ---------------- launch ----------------
extern "C" void kernel_launch(void* const* d_in, const int* in_sizes, int n_in,
                              void* d_out, int out_size) {
  const float* x    = (const float*)d_in[0];
  const float* W_ih = (const float*)d_in[1];
  const float* W_hh = (const float*)d_in[2];
  const float* b_ih = (const float*)d_in[3];
  const float* b_hh = (const float*)d_in[4];
  const float* fc_w = (const float*)d_in[5];
  const float* fc_b = (const float*)d_in[6];
  float* out = (float*)d_out;

  static bool init = false;
  if (!init) {
    cudaFuncSetAttribute(lstm_kernel,
                         cudaFuncAttributeMaxDynamicSharedMemorySize, SMEM_TOTAL);
    init = true;
  }

  reset_kernel<<<1, 512>>>();
  zring_kernel<<<64, 256>>>();
  xprep_kernel<<<65536, 256>>>(x);
  lstm_kernel<<<NBG * NGG, NTHR, SMEM_TOTAL>>>(W_ih, W_hh, b_ih, b_hh);
  fc_kernel<<<256, 256>>>(fc_w, fc_b, out);
}